// round 9
// baseline (speedup 1.0000x reference)
#include <cuda_runtime.h>
#include <cuda_fp16.h>
#include <math.h>
#include <stdint.h>

// Problem dims (fixed by the dataset)
constexpr int BATCH = 16384;
constexpr int D_IN  = 2048;
constexpr int H1D   = 1024;
constexpr int H2D   = 512;
constexpr int DLAT  = 256;
constexpr int KCODE = 1024;

// fp16 staging scales (powers of 2; exact rescale in epilogue)
constexpr float SA = 16.0f;
constexpr float SB = 32.0f;
constexpr float INVS = 1.0f / (16.0f * 32.0f);

// ---------------------------------------------------------------------------
// Scratch (allocation-free contract: __device__ globals)
// ---------------------------------------------------------------------------
__device__ float g_h1[(size_t)BATCH * H1D];     // enc h1 / VQ scores / dec h1
__device__ float g_h2[(size_t)BATCH * H2D];     // enc h2 / dec h2
__device__ float g_res[(size_t)BATCH * DLAT];   // z after LN, then running residual
__device__ float g_zq[(size_t)BATCH * DLAT];    // z_q_total
__device__ float g_vloss[BATCH];
__device__ int   g_idx[BATCH * 3];
__device__ float g_cbn[3 * KCODE];
// pre-split fp16 weights, [N,K] row-major, scaled by SB
__device__ __half g_w1h[(size_t)H1D * D_IN], g_w1l[(size_t)H1D * D_IN];
__device__ __half g_w2h[(size_t)H2D * H1D], g_w2l[(size_t)H2D * H1D];
__device__ __half g_w3h[(size_t)DLAT * H2D], g_w3l[(size_t)DLAT * H2D];
__device__ __half g_d1h[(size_t)H2D * DLAT], g_d1l[(size_t)H2D * DLAT];
__device__ __half g_d2h[(size_t)H1D * H2D], g_d2l[(size_t)H1D * H2D];
__device__ __half g_d3h[(size_t)D_IN * H1D], g_d3l[(size_t)D_IN * H1D];
__device__ __half g_cbh[(size_t)3 * KCODE * DLAT];   // hi-only, scaled by SB

// ---------------------------------------------------------------------------
// Helpers
// ---------------------------------------------------------------------------
__device__ __forceinline__ uint32_t smem_u32(const void* p) {
    uint32_t a;
    asm("{ .reg .u64 t; cvta.to.shared.u64 t, %1; cvt.u32.u64 %0, t; }"
        : "=r"(a) : "l"(p));
    return a;
}

__device__ __forceinline__ uint32_t pack_h2(__half a, __half b) {
    __half2 h = __halves2half2(a, b);
    return *(uint32_t*)&h;
}

// split x,y (pre-scaled) into packed fp16 hi and lo half2
__device__ __forceinline__ void split2(float x, float y,
                                       uint32_t& hi, uint32_t& lo) {
    __half hx = __float2half_rn(x), hy = __float2half_rn(y);
    __half lx = __float2half_rn(x - __half2float(hx));
    __half ly = __float2half_rn(y - __half2float(hy));
    hi = pack_h2(hx, hy);
    lo = pack_h2(lx, ly);
}

// m16n8k16 fp16 MMA (row.col), fp32 accumulate
__device__ __forceinline__ void mma16(float d[4], const uint32_t a[4],
                                      const uint32_t b[2]) {
    asm volatile(
        "mma.sync.aligned.m16n8k16.row.col.f32.f16.f16.f32 "
        "{%0,%1,%2,%3}, {%4,%5,%6,%7}, {%8,%9}, {%0,%1,%2,%3};\n"
        : "+f"(d[0]), "+f"(d[1]), "+f"(d[2]), "+f"(d[3])
        : "r"(a[0]), "r"(a[1]), "r"(a[2]), "r"(a[3]),
          "r"(b[0]), "r"(b[1]));
}

__device__ __forceinline__ void ldsm4(uint32_t& r0, uint32_t& r1,
                                      uint32_t& r2, uint32_t& r3, uint32_t addr) {
    asm volatile("ldmatrix.sync.aligned.m8n8.x4.shared.b16 {%0,%1,%2,%3}, [%4];"
                 : "=r"(r0), "=r"(r1), "=r"(r2), "=r"(r3) : "r"(addr));
}

__device__ __forceinline__ void cp16(uint32_t dst, const void* src) {
    asm volatile("cp.async.cg.shared.global [%0], [%1], 16;\n"
                 :: "r"(dst), "l"(src));
}
__device__ __forceinline__ void cp_commit() {
    asm volatile("cp.async.commit_group;\n");
}
__device__ __forceinline__ void cp_wait0() {
    asm volatile("cp.async.wait_group 0;\n" ::: "memory");
}

// fp16 tile: [128 rows][16 halves] = 32B rows.
// 16B group g of row r stored at group (g ^ ((r>>2)&1)).  Conflict-free for
// staging STS.128, cp.async, and every 8-address ldmatrix phase.
__device__ __forceinline__ uint32_t tile_addr(uint32_t row, uint32_t g) {
    return row * 32 + ((g ^ ((row >> 2) & 1u)) << 4);
}

// ---------------------------------------------------------------------------
// fp16 mma.sync GEMM with pre-split B: C = act((A @ B^T)*INVS + bias)
//   A fp32 [M,K]; Bhi/Blo fp16 [N,K] pre-scaled by SB.
//   NTERMS==3: A split (hi+lo) x B (hi+lo), products hh + hl + lh
//   NTERMS==1: single-pass (A rounded, Bhi)
// Tile 128x128, BK=16, 256 threads, 8 warps (2m x 4n).
// B tiles via cp.async (no register path); A via LDG+split+STS.
// NT3 MMA schedule is term-major per mt (dep distance 4, not 1).
// ---------------------------------------------------------------------------
template <int NTERMS, bool RELU, bool HASBIAS>
__global__ __launch_bounds__(256, 2)
void mma_gemm_h(const float* __restrict__ A, const __half* __restrict__ Bhi,
                const __half* __restrict__ Blo, const float* __restrict__ bias,
                float* __restrict__ C, int N, int Kd)
{
    extern __shared__ char smem[];
    const uint32_t smb = smem_u32(smem);
    constexpr int TILEB = 4096;
    constexpr int STAGE = (NTERMS == 3) ? 16384 : 8192;

    const int tid  = threadIdx.x;
    const int wid  = tid >> 5;
    const int lane = tid & 31;
    const int wm   = wid & 1;       // 0..1 -> 64 rows
    const int wn   = wid >> 1;      // 0..3 -> 32 cols

    const int nk = Kd >> 4;         // BK=16 chunks
    const float* Ag  = A   + (size_t)(blockIdx.y * 128) * Kd;
    const __half* Bh = Bhi + (size_t)(blockIdx.x * 128) * Kd;
    const __half* Bl = (NTERMS == 3) ? Blo + (size_t)(blockIdx.x * 128) * Kd : nullptr;

    // staging role: thread -> (row r, 8-element group hf of the 16-wide chunk)
    const int r  = tid >> 1;
    const int hf = tid & 1;
    const uint32_t soff = tile_addr((uint32_t)r, (uint32_t)hf);

    // ldmatrix per-lane address components
    const uint32_t amat   = (uint32_t)lane >> 3;
    const uint32_t arow_l = (uint32_t)(lane & 7) + ((amat & 1u) << 3);
    const uint32_t ag     = amat >> 1;
    const uint32_t bmat   = (uint32_t)lane >> 3;
    const uint32_t brow_l = (uint32_t)(lane & 7) + ((bmat >> 1) << 3);
    const uint32_t bg     = bmat & 1u;

    float acc[4][4][4];
#pragma unroll
    for (int i = 0; i < 4; i++)
#pragma unroll
        for (int j = 0; j < 4; j++)
#pragma unroll
            for (int q = 0; q < 4; q++) acc[i][j][q] = 0.0f;

    float4 va[2];

    auto ldgA = [&](int k0) {
        const float4* pa = (const float4*)(Ag + (size_t)r * Kd + k0 * 16 + hf * 8);
        va[0] = pa[0]; va[1] = pa[1];
    };

    auto cpB = [&](int k0, int s) {
        uint32_t dst = smb + (uint32_t)(s * STAGE) + TILEB + soff;
        cp16(dst, Bh + (size_t)r * Kd + k0 * 16 + hf * 8);
        if (NTERMS == 3)
            cp16(dst + 2 * TILEB, Bl + (size_t)r * Kd + k0 * 16 + hf * 8);
        cp_commit();
    };

    auto storeA = [&](int s) {
        char* st = smem + s * STAGE;
        uint4 ha;
        if (NTERMS == 3) {
            uint4 la;
            split2(SA * va[0].x, SA * va[0].y, ha.x, la.x);
            split2(SA * va[0].z, SA * va[0].w, ha.y, la.y);
            split2(SA * va[1].x, SA * va[1].y, ha.z, la.z);
            split2(SA * va[1].z, SA * va[1].w, ha.w, la.w);
            *(uint4*)(st + soff)             = ha;
            *(uint4*)(st + 2 * TILEB + soff) = la;
        } else {
            ha.x = pack_h2(__float2half_rn(SA * va[0].x), __float2half_rn(SA * va[0].y));
            ha.y = pack_h2(__float2half_rn(SA * va[0].z), __float2half_rn(SA * va[0].w));
            ha.z = pack_h2(__float2half_rn(SA * va[1].x), __float2half_rn(SA * va[1].y));
            ha.w = pack_h2(__float2half_rn(SA * va[1].z), __float2half_rn(SA * va[1].w));
            *(uint4*)(st + soff) = ha;
        }
    };

    // prologue: fill stage 0
    cpB(0, 0);
    ldgA(0);
    storeA(0);
    cp_wait0();
    __syncthreads();

    for (int k0 = 0; k0 < nk; k0++) {
        if (k0 + 1 < nk) {
            cpB(k0 + 1, (k0 + 1) & 1);
            ldgA(k0 + 1);
        }

        const uint32_t stb = smb + (uint32_t)((k0 & 1) * STAGE);

        // B fragments
        uint32_t bhf[4][2], blf[4][2];
#pragma unroll
        for (int p = 0; p < 2; p++) {
            uint32_t nrow = (uint32_t)(wn * 32 + p * 16) + brow_l;
            uint32_t ba = stb + TILEB + tile_addr(nrow, bg);
            ldsm4(bhf[p * 2][0], bhf[p * 2][1], bhf[p * 2 + 1][0], bhf[p * 2 + 1][1], ba);
            if (NTERMS == 3)
                ldsm4(blf[p * 2][0], blf[p * 2][1], blf[p * 2 + 1][0], blf[p * 2 + 1][1],
                      ba + 2 * TILEB);
        }
#pragma unroll
        for (int mt = 0; mt < 4; mt++) {
            uint32_t arow = (uint32_t)(wm * 64 + mt * 16) + arow_l;
            uint32_t aa = stb + tile_addr(arow, ag);
            uint32_t ah[4], al[4];
            ldsm4(ah[0], ah[1], ah[2], ah[3], aa);
            if (NTERMS == 3)
                ldsm4(al[0], al[1], al[2], al[3], aa + 2 * TILEB);
            // term-major: 4 independent MMAs per pass (dep distance 4);
            // per-accumulator order stays hh, hl, lh (bit-identical numerics)
#pragma unroll
            for (int nt = 0; nt < 4; nt++) mma16(acc[mt][nt], ah, bhf[nt]);
            if (NTERMS == 3) {
#pragma unroll
                for (int nt = 0; nt < 4; nt++) mma16(acc[mt][nt], ah, blf[nt]);
#pragma unroll
                for (int nt = 0; nt < 4; nt++) mma16(acc[mt][nt], al, bhf[nt]);
            }
        }

        if (k0 + 1 < nk) {
            storeA((k0 + 1) & 1);
            cp_wait0();
        }
        __syncthreads();
    }

    // ---- epilogue (rescale by INVS, then bias/ReLU) ----
    const int row0 = blockIdx.y * 128 + wm * 64 + (lane >> 2);
    const int col0 = blockIdx.x * 128 + wn * 32 + (lane & 3) * 2;
#pragma unroll
    for (int mt = 0; mt < 4; mt++) {
#pragma unroll
        for (int nt = 0; nt < 4; nt++) {
            int rr = row0 + mt * 16;
            int cc = col0 + nt * 8;
            float b0 = 0.f, b1 = 0.f;
            if (HASBIAS) { b0 = __ldg(bias + cc); b1 = __ldg(bias + cc + 1); }
            float2 v0, v1;
            v0.x = acc[mt][nt][0] * INVS + b0; v0.y = acc[mt][nt][1] * INVS + b1;
            v1.x = acc[mt][nt][2] * INVS + b0; v1.y = acc[mt][nt][3] * INVS + b1;
            if (RELU) {
                v0.x = fmaxf(v0.x, 0.f); v0.y = fmaxf(v0.y, 0.f);
                v1.x = fmaxf(v1.x, 0.f); v1.y = fmaxf(v1.y, 0.f);
            }
            *(float2*)(C + (size_t)rr * N + cc)       = v0;
            *(float2*)(C + (size_t)(rr + 8) * N + cc) = v1;
        }
    }
}

// ---------------------------------------------------------------------------
// Prep: transpose + scale + split  W[K,N] f32 -> Thi/Tlo[N,K] half (x SB)
// ---------------------------------------------------------------------------
__global__ __launch_bounds__(256)
void transpose_convert(const float* __restrict__ W, __half* __restrict__ Thi,
                       __half* __restrict__ Tlo, int K, int N)
{
    __shared__ float tile[32][33];
    int n0 = blockIdx.x * 32;
    int k0 = blockIdx.y * 32;
#pragma unroll
    for (int i = 0; i < 32; i += 8)
        tile[threadIdx.y + i][threadIdx.x] =
            W[(size_t)(k0 + threadIdx.y + i) * N + n0 + threadIdx.x];
    __syncthreads();
#pragma unroll
    for (int i = 0; i < 32; i += 8) {
        float v = SB * tile[threadIdx.x][threadIdx.y + i];
        __half h = __float2half_rn(v);
        __half l = __float2half_rn(v - __half2float(h));
        size_t o = (size_t)(n0 + threadIdx.y + i) * K + k0 + threadIdx.x;
        Thi[o] = h;
        Tlo[o] = l;
    }
}

// Codebooks are already [N,K]; scores only need hi (NT=1).
__global__ __launch_bounds__(256)
void convert_cb_kernel(const float* __restrict__ cb0, const float* __restrict__ cb1,
                       const float* __restrict__ cb2, __half* __restrict__ out)
{
    int i = blockIdx.x * 256 + threadIdx.x;       // < 3*KCODE*DLAT
    const int S = KCODE * DLAT;
    const float* src = (i < S) ? cb0 : (i < 2 * S ? cb1 : cb2);
    out[i] = __float2half_rn(SB * src[i % S]);
}

// ---------------------------------------------------------------------------
// LayerNorm over DLAT=256, warp per row
// ---------------------------------------------------------------------------
__global__ __launch_bounds__(256)
void ln_kernel(float* __restrict__ z, const float* __restrict__ g,
               const float* __restrict__ b)
{
    int row  = blockIdx.x * 8 + (threadIdx.x >> 5);
    int lane = threadIdx.x & 31;
    float* zr = z + (size_t)row * DLAT;

    float v[8];
    float s = 0.f;
#pragma unroll
    for (int i = 0; i < 8; i++) { v[i] = zr[lane + 32 * i]; s += v[i]; }
#pragma unroll
    for (int o = 16; o; o >>= 1) s += __shfl_xor_sync(0xffffffffu, s, o);
    float mu = s * (1.0f / 256.0f);

    float s2 = 0.f;
#pragma unroll
    for (int i = 0; i < 8; i++) { float d = v[i] - mu; s2 += d * d; }
#pragma unroll
    for (int o = 16; o; o >>= 1) s2 += __shfl_xor_sync(0xffffffffu, s2, o);
    float var = s2 * (1.0f / 256.0f);
    float rs  = 1.0f / sqrtf(var + 1e-5f);

#pragma unroll
    for (int i = 0; i < 8; i++) {
        int col = lane + 32 * i;
        zr[col] = (v[i] - mu) * rs * g[col] + b[col];
    }
}

// ---------------------------------------------------------------------------
// Codebook row norms: warp per code (fp32 codebooks)
// ---------------------------------------------------------------------------
__global__ __launch_bounds__(256)
void cbnorm_kernel(const float* __restrict__ cb0, const float* __restrict__ cb1,
                   const float* __restrict__ cb2, float* __restrict__ cbn)
{
    int code = blockIdx.x * 8 + (threadIdx.x >> 5);
    int lane = threadIdx.x & 31;
    const float* cb = (code < KCODE) ? cb0 : (code < 2 * KCODE ? cb1 : cb2);
    const float* c  = cb + (size_t)(code & (KCODE - 1)) * DLAT;
    float s = 0.f;
#pragma unroll
    for (int i = 0; i < 8; i++) { float v = c[lane + 32 * i]; s += v * v; }
#pragma unroll
    for (int o = 16; o; o >>= 1) s += __shfl_xor_sync(0xffffffffu, s, o);
    if (lane == 0) cbn[code] = s;
}

// ---------------------------------------------------------------------------
// Fused VQ step with exact refinement (approx scores -> exact fp32 recheck
// of all candidates within MARGIN). Warp per row.
// ---------------------------------------------------------------------------
constexpr float VQ_MARGIN = 0.05f;

__global__ __launch_bounds__(256)
void vq_step(float* __restrict__ res, const float* __restrict__ scores,
             const float* __restrict__ cbn, const float* __restrict__ cb,
             float* __restrict__ zq, float* __restrict__ vloss,
             int* __restrict__ idx_out, int stage)
{
    int row  = blockIdx.x * 8 + (threadIdx.x >> 5);
    int lane = threadIdx.x & 31;

    float* r = res + (size_t)row * DLAT;
    float rv[8];
    float s = 0.f;
#pragma unroll
    for (int i = 0; i < 8; i++) { rv[i] = r[lane + 32 * i]; s += rv[i] * rv[i]; }
#pragma unroll
    for (int o = 16; o; o >>= 1) s += __shfl_xor_sync(0xffffffffu, s, o);
    const float rnorm = s;

    // pass 1: approximate min distance (value only)
    const float* sr = scores + (size_t)row * KCODE;
    float amin = INFINITY;
    float dv[32];
#pragma unroll 4
    for (int j = 0; j < 32; j++) {
        int n = lane + 32 * j;
        float d = (rnorm - 2.0f * sr[n]) + cbn[n];
        dv[j] = d;
        amin = fminf(amin, d);
    }
#pragma unroll
    for (int o = 16; o; o >>= 1)
        amin = fminf(amin, __shfl_xor_sync(0xffffffffu, amin, o));

    // pass 2: candidate mask per lane (bit j <-> code lane + 32j)
    const float thresh = amin + VQ_MARGIN;
    uint32_t cmask = 0;
#pragma unroll
    for (int j = 0; j < 32; j++)
        if (dv[j] <= thresh) cmask |= (1u << j);

    // warp-cooperative exact refinement, one candidate per iteration
    float bestv = INFINITY;
    int   bestn = KCODE;
    for (;;) {
        uint32_t ball = __ballot_sync(0xffffffffu, cmask != 0);
        if (!ball) break;
        int src = __ffs(ball) - 1;
        uint32_t m = __shfl_sync(0xffffffffu, cmask, src);
        int j = __ffs(m) - 1;
        if (lane == src) cmask &= cmask - 1;   // clear lowest bit
        int n = src + 32 * j;

        const float* c = cb + (size_t)n * DLAT;
        float dot = 0.f;
#pragma unroll
        for (int i = 0; i < 8; i++) dot += rv[i] * c[lane + 32 * i];
#pragma unroll
        for (int o = 16; o; o >>= 1) dot += __shfl_xor_sync(0xffffffffu, dot, o);

        float d = (rnorm - 2.0f * dot) + cbn[n];
        if (d < bestv || (d == bestv && n < bestn)) { bestv = d; bestn = n; }
    }
    const int bi = bestn;
    if (lane == 0) idx_out[row * 3 + stage] = bi;

    // straight-through update (replicates JAX numerics exactly)
    const float* c = cb + (size_t)bi * DLAT;
    float* q = zq + (size_t)row * DLAT;
    float se = 0.f;
#pragma unroll
    for (int i = 0; i < 8; i++) {
        int col = lane + 32 * i;
        float ev = c[col];
        float diff = rv[i] - ev;
        se += diff * diff;
        float t   = ev - rv[i];      // sg(e - r)
        float zqe = rv[i] + t;       // straight-through z_q
        r[col] = rv[i] - zqe;        // residual - sg(z_q)
        q[col] = (stage == 0) ? zqe : (q[col] + zqe);
    }
#pragma unroll
    for (int o = 16; o; o >>= 1) se += __shfl_xor_sync(0xffffffffu, se, o);
    if (lane == 0) {
        float m = se * (1.0f / 256.0f);
        float l = m + 0.25f * m;
        vloss[row] = (stage == 0) ? l : (vloss[row] + l);
    }
}

// ---------------------------------------------------------------------------
// Finalize: recon loss, total loss, idx -> float
// ---------------------------------------------------------------------------
__global__ __launch_bounds__(256)
void finalize_kernel(const float* __restrict__ x, const float* __restrict__ xhat,
                     const float* __restrict__ vloss, const int* __restrict__ idx,
                     float* __restrict__ out_loss, float* __restrict__ out_idx)
{
    int row  = blockIdx.x * 8 + (threadIdx.x >> 5);
    int lane = threadIdx.x & 31;

    const float* xr = x    + (size_t)row * D_IN;
    const float* hr = xhat + (size_t)row * D_IN;
    float s = 0.f;
#pragma unroll 8
    for (int i = 0; i < 64; i++) {
        int col = lane + 32 * i;
        float d = hr[col] - xr[col];
        s += d * d;
    }
#pragma unroll
    for (int o = 16; o; o >>= 1) s += __shfl_xor_sync(0xffffffffu, s, o);
    if (lane == 0) {
        float recon = s * (1.0f / 2048.0f);
        out_loss[row] = vloss[row] + recon;
    }
    if (lane < 3) out_idx[row * 3 + lane] = (float)idx[row * 3 + lane];
}

// ---------------------------------------------------------------------------
// Launch
// ---------------------------------------------------------------------------
extern "C" void kernel_launch(void* const* d_in, const int* in_sizes, int n_in,
                              void* d_out, int out_size)
{
    const float* x      = (const float*)d_in[0];
    const float* encW1  = (const float*)d_in[1];
    const float* encb1  = (const float*)d_in[2];
    const float* encW2  = (const float*)d_in[3];
    const float* encb2  = (const float*)d_in[4];
    const float* encW3  = (const float*)d_in[5];
    const float* encb3  = (const float*)d_in[6];
    const float* ln_g   = (const float*)d_in[7];
    const float* ln_b   = (const float*)d_in[8];
    const float* cb0    = (const float*)d_in[9];
    const float* cb1    = (const float*)d_in[10];
    const float* cb2    = (const float*)d_in[11];
    const float* decW1  = (const float*)d_in[12];
    const float* decb1  = (const float*)d_in[13];
    const float* decW2  = (const float*)d_in[14];
    const float* decb2  = (const float*)d_in[15];
    const float* decW3  = (const float*)d_in[16];
    const float* decb3  = (const float*)d_in[17];

    float *h1, *h2, *res, *zq, *vloss, *cbn;
    __half *w1h, *w1l, *w2h, *w2l, *w3h, *w3l;
    __half *d1h, *d1l, *d2h, *d2l, *d3h, *d3l, *cbh;
    int* idx;
    cudaGetSymbolAddress((void**)&h1, g_h1);
    cudaGetSymbolAddress((void**)&h2, g_h2);
    cudaGetSymbolAddress((void**)&res, g_res);
    cudaGetSymbolAddress((void**)&zq, g_zq);
    cudaGetSymbolAddress((void**)&vloss, g_vloss);
    cudaGetSymbolAddress((void**)&cbn, g_cbn);
    cudaGetSymbolAddress((void**)&idx, g_idx);
    cudaGetSymbolAddress((void**)&w1h, g_w1h); cudaGetSymbolAddress((void**)&w1l, g_w1l);
    cudaGetSymbolAddress((void**)&w2h, g_w2h); cudaGetSymbolAddress((void**)&w2l, g_w2l);
    cudaGetSymbolAddress((void**)&w3h, g_w3h); cudaGetSymbolAddress((void**)&w3l, g_w3l);
    cudaGetSymbolAddress((void**)&d1h, g_d1h); cudaGetSymbolAddress((void**)&d1l, g_d1l);
    cudaGetSymbolAddress((void**)&d2h, g_d2h); cudaGetSymbolAddress((void**)&d2l, g_d2l);
    cudaGetSymbolAddress((void**)&d3h, g_d3h); cudaGetSymbolAddress((void**)&d3l, g_d3l);
    cudaGetSymbolAddress((void**)&cbh, g_cbh);

    float* xhat     = (float*)d_out;
    float* out_loss = xhat + (size_t)BATCH * D_IN;
    float* out_idx  = out_loss + BATCH;

    const int SMEM3 = 2 * 16384;   // 32 KB
    const int SMEM1 = 2 * 8192;    // 16 KB
    cudaFuncSetAttribute((const void*)mma_gemm_h<3, true,  true >, cudaFuncAttributeMaxDynamicSharedMemorySize, SMEM3);
    cudaFuncSetAttribute((const void*)mma_gemm_h<3, false, true >, cudaFuncAttributeMaxDynamicSharedMemorySize, SMEM3);
    cudaFuncSetAttribute((const void*)mma_gemm_h<1, false, false>, cudaFuncAttributeMaxDynamicSharedMemorySize, SMEM1);
    cudaFuncSetAttribute((const void*)mma_gemm_h<1, true,  true >, cudaFuncAttributeMaxDynamicSharedMemorySize, SMEM1);
    cudaFuncSetAttribute((const void*)mma_gemm_h<1, false, true >, cudaFuncAttributeMaxDynamicSharedMemorySize, SMEM1);

    const dim3 blk(256);
    const dim3 tblk(32, 8);
    const int MB = BATCH / 128;          // 128
    const int warpGrid = BATCH / 8;      // 2048

    // ---- prep: transpose+split weights; codebook hi; codebook norms ----
    transpose_convert<<<dim3(H1D / 32, D_IN / 32), tblk>>>(encW1, w1h, w1l, D_IN, H1D);
    transpose_convert<<<dim3(H2D / 32, H1D / 32), tblk>>>(encW2, w2h, w2l, H1D, H2D);
    transpose_convert<<<dim3(DLAT / 32, H2D / 32), tblk>>>(encW3, w3h, w3l, H2D, DLAT);
    transpose_convert<<<dim3(H2D / 32, DLAT / 32), tblk>>>(decW1, d1h, d1l, DLAT, H2D);
    transpose_convert<<<dim3(H1D / 32, H2D / 32), tblk>>>(decW2, d2h, d2l, H2D, H1D);
    transpose_convert<<<dim3(D_IN / 32, H1D / 32), tblk>>>(decW3, d3h, d3l, H1D, D_IN);
    convert_cb_kernel<<<3 * KCODE * DLAT / 256, blk>>>(cb0, cb1, cb2, cbh);
    cbnorm_kernel<<<3 * KCODE / 8, blk>>>(cb0, cb1, cb2, cbn);

    // ---- encoder (fp16 split x3 ~ fp32 accuracy; feeds argmin) ----
    mma_gemm_h<3, true,  true ><<<dim3(H1D / 128, MB), blk, SMEM3>>>(x,  w1h, w1l, encb1, h1,  H1D,  D_IN);
    mma_gemm_h<3, true,  true ><<<dim3(H2D / 128, MB), blk, SMEM3>>>(h1, w2h, w2l, encb2, h2,  H2D,  H1D);
    mma_gemm_h<3, false, true ><<<dim3(DLAT / 128, MB), blk, SMEM3>>>(h2, w3h, w3l, encb3, res, DLAT, H2D);

    ln_kernel<<<warpGrid, blk>>>(res, ln_g, ln_b);

    // ---- residual VQ: approx scores (fp16 single) + exact refinement ----
    for (int s = 0; s < 3; s++) {
        const float* cb = (s == 0) ? cb0 : (s == 1 ? cb1 : cb2);
        mma_gemm_h<1, false, false><<<dim3(KCODE / 128, MB), blk, SMEM1>>>(res, cbh + (size_t)s * KCODE * DLAT, nullptr, nullptr, h1, KCODE, DLAT);
        vq_step<<<warpGrid, blk>>>(res, h1, cbn + s * KCODE, cb, zq, vloss, idx, s);
    }

    // ---- decoder (fp16 single-pass; post-argmin, tolerance-safe) ----
    mma_gemm_h<1, true,  true ><<<dim3(H2D / 128, MB), blk, SMEM1>>>(zq, d1h, nullptr, decb1, h2,   H2D,  DLAT);
    mma_gemm_h<1, true,  true ><<<dim3(H1D / 128, MB), blk, SMEM1>>>(h2, d2h, nullptr, decb2, h1,   H1D,  H2D);
    mma_gemm_h<1, false, true ><<<dim3(D_IN / 128, MB), blk, SMEM1>>>(h1, d3h, nullptr, decb3, xhat, D_IN, H1D);

    finalize_kernel<<<warpGrid, blk>>>(x, xhat, vloss, idx, out_loss, out_idx);
}